// round 3
// baseline (speedup 1.0000x reference)
#include <cuda_runtime.h>
#include <cstdint>

#define NN   50000
#define EE   640000
#define FIN  128
#define HID  128
#define FOUT 64

// ---------------- device scratch (no allocations allowed) ----------------
__device__ __align__(16) float g_buf0[NN * HID];   // H (layer activations)
__device__ __align__(16) float g_buf1[NN * HID];   // P = H @ W
__device__ __align__(16) float g_xres[NN * HID];   // residual x @ Wres + bres
__device__ float g_dinv[NN];
__device__ float g_nself[NN];
__device__ int   g_deg[NN];
__device__ int   g_offs[NN];
__device__ int   g_cursor[NN];
__device__ int   g_csr_src[EE];
__device__ float g_csr_ne[EE];

// buffer selectors: resolve device-global scratch inside device code
// 0 = external pointer, 1 = g_buf0, 2 = g_buf1, 3 = g_xres
__device__ __forceinline__ const float* pick_src(int sel, const float* ext) {
    if (sel == 1) return g_buf0;
    if (sel == 2) return g_buf1;
    if (sel == 3) return g_xres;
    return ext;
}
__device__ __forceinline__ float* pick_dst(int sel, float* ext) {
    if (sel == 1) return g_buf0;
    if (sel == 2) return g_buf1;
    if (sel == 3) return g_xres;
    return ext;
}

// ---------------- graph preprocessing ----------------
// edge_index arrives as int32 (harness converts int64 -> int32), layout [2, E]
__global__ void k_zero_deg(int n) {
    int i = blockIdx.x * blockDim.x + threadIdx.x;
    if (i < n) g_deg[i] = 0;
}

__global__ void k_count(const int* __restrict__ ei, int e, int n) {
    int i = blockIdx.x * blockDim.x + threadIdx.x;
    if (i < e) {
        int dst = ei[e + i];
        if (dst >= 0 && dst < n) atomicAdd(&g_deg[dst], 1);
    }
}

__global__ void k_norm(int n) {
    int i = blockIdx.x * blockDim.x + threadIdx.x;
    if (i < n) {
        float d = (float)g_deg[i] + 1.0f;   // +1 self loop
        g_dinv[i]  = rsqrtf(d);
        g_nself[i] = 1.0f / d;
    }
}

// single-block exclusive scan of g_deg -> g_offs, g_cursor
__global__ void k_scan(int n) {
    __shared__ int part[1024];
    int tid = threadIdx.x;
    int chunk = (n + 1023) / 1024;
    int base = tid * chunk;
    int s = 0;
    for (int i = 0; i < chunk; i++) {
        int idx = base + i;
        if (idx < n) s += g_deg[idx];
    }
    part[tid] = s;
    __syncthreads();
    for (int off = 1; off < 1024; off <<= 1) {
        int v = 0;
        if (tid >= off) v = part[tid - off];
        __syncthreads();
        part[tid] += v;
        __syncthreads();
    }
    int run = (tid == 0) ? 0 : part[tid - 1];
    for (int i = 0; i < chunk; i++) {
        int idx = base + i;
        if (idx < n) {
            g_offs[idx]   = run;
            g_cursor[idx] = run;
            run += g_deg[idx];
        }
    }
}

__global__ void k_fill(const int* __restrict__ ei, int e, int n) {
    int i = blockIdx.x * blockDim.x + threadIdx.x;
    if (i < e) {
        int src = ei[i];
        int dst = ei[e + i];
        if (src < 0 || src >= n || dst < 0 || dst >= n) return;
        int pos = atomicAdd(&g_cursor[dst], 1);
        if (pos >= 0 && pos < EE) {
            g_csr_src[pos] = src;
            g_csr_ne[pos]  = g_dinv[src] * g_dinv[dst];
        }
    }
}

// ---------------- GEMM: Y[n,FO] = X[n,128] @ W[128,FO] (+ bias) ----------------
// 64 rows per block, K-chunked (32), W+X tiles in smem, 4-col x RPT-row register blocking.
template <int FO>
__global__ __launch_bounds__(256) void k_gemm(
    const float* Xext, int xsel, const float* __restrict__ W,
    const float* __restrict__ bias, float* Yext, int ysel, int n)
{
    const float* __restrict__ X = pick_src(xsel, Xext);
    float* __restrict__ Y       = pick_dst(ysel, Yext);

    constexpr int TJ  = FO / 4;          // thread groups along columns
    constexpr int TR  = 256 / TJ;        // thread groups along rows
    constexpr int RPT = 64 / TR;         // rows per thread
    constexpr int XS_STRIDE = 33;        // padded to kill bank conflicts

    __shared__ float ws[32 * FO];
    __shared__ float xs[64 * XS_STRIDE];

    int tid  = threadIdx.x;
    int row0 = blockIdx.x * 64;
    int tj   = tid % TJ;
    int tr   = tid / TJ;

    float acc[RPT][4];
#pragma unroll
    for (int r = 0; r < RPT; r++)
#pragma unroll
        for (int c = 0; c < 4; c++) acc[r][c] = 0.0f;

    for (int kc = 0; kc < 128; kc += 32) {
        // load W chunk (32 x FO contiguous floats)
        constexpr int WLD = (32 * FO / 4) / 256;
        const float4* Wg = (const float4*)(W + kc * FO);
        float4* wsv = (float4*)ws;
#pragma unroll
        for (int i = 0; i < WLD; i++) wsv[tid + i * 256] = Wg[tid + i * 256];

        // load X chunk (64 x 32) into padded smem
#pragma unroll
        for (int i = 0; i < 2; i++) {
            int idx = tid + i * 256;        // 0..511
            int r   = idx >> 3;
            int c4  = idx & 7;
            int grow = row0 + r;
            float4 v = make_float4(0.f, 0.f, 0.f, 0.f);
            if (grow < n)
                v = ((const float4*)(X + (size_t)grow * 128 + kc))[c4];
            float* dp = &xs[r * XS_STRIDE + c4 * 4];
            dp[0] = v.x; dp[1] = v.y; dp[2] = v.z; dp[3] = v.w;
        }
        __syncthreads();

#pragma unroll
        for (int k = 0; k < 32; k++) {
            float4 w4 = ((const float4*)(ws + k * FO))[tj];
#pragma unroll
            for (int ri = 0; ri < RPT; ri++) {
                float xv = xs[(tr * RPT + ri) * XS_STRIDE + k];
                acc[ri][0] += xv * w4.x;
                acc[ri][1] += xv * w4.y;
                acc[ri][2] += xv * w4.z;
                acc[ri][3] += xv * w4.w;
            }
        }
        __syncthreads();
    }

    float4 b4 = make_float4(0.f, 0.f, 0.f, 0.f);
    if (bias) b4 = ((const float4*)bias)[tj];
#pragma unroll
    for (int ri = 0; ri < RPT; ri++) {
        int grow = row0 + tr * RPT + ri;
        if (grow < n) {
            float4 o;
            o.x = acc[ri][0] + b4.x;
            o.y = acc[ri][1] + b4.y;
            o.z = acc[ri][2] + b4.z;
            o.w = acc[ri][3] + b4.w;
            ((float4*)(Y + (size_t)grow * FO))[tj] = o;
        }
    }
}

// ---------------- fused GCN aggregation + bias + residual + ReLU ----------------
// one warp per destination node; each lane owns 4 features (float4)
__global__ __launch_bounds__(256) void k_gather(
    int psel,                        // P = H @ W   (selector)
    int rsel,                        // residual (0 = none)
    const float* __restrict__ bias,  // [128]
    int osel,                        // Hout selector
    int n)
{
    const float* __restrict__ P   = pick_src(psel, nullptr);
    const float* __restrict__ res = (rsel == 0) ? nullptr : pick_src(rsel, nullptr);
    float* __restrict__ Hout      = pick_dst(osel, nullptr);

    int warp = (blockIdx.x * blockDim.x + threadIdx.x) >> 5;
    int lane = threadIdx.x & 31;
    if (warp >= n) return;
    int node = warp;

    float ns = g_nself[node];
    float4 pv = ((const float4*)(P + (size_t)node * 128))[lane];
    float ax = pv.x * ns, ay = pv.y * ns, az = pv.z * ns, aw = pv.w * ns;

    int start = g_offs[node];
    int d     = g_deg[node];
    for (int i = 0; i < d; i++) {
        int e = start + i;
        int s   = g_csr_src[e];
        float ne = g_csr_ne[e];
        float4 hv = ((const float4*)(P + (size_t)s * 128))[lane];
        ax += hv.x * ne;
        ay += hv.y * ne;
        az += hv.z * ne;
        aw += hv.w * ne;
    }

    float4 b4 = ((const float4*)bias)[lane];
    ax += b4.x; ay += b4.y; az += b4.z; aw += b4.w;
    if (res) {
        float4 r4 = ((const float4*)(res + (size_t)node * 128))[lane];
        ax += r4.x; ay += r4.y; az += r4.z; aw += r4.w;
    }
    float4 o;
    o.x = fmaxf(ax, 0.f);
    o.y = fmaxf(ay, 0.f);
    o.z = fmaxf(az, 0.f);
    o.w = fmaxf(aw, 0.f);
    ((float4*)(Hout + (size_t)node * 128))[lane] = o;
}

// ---------------- launch ----------------
extern "C" void kernel_launch(void* const* d_in, const int* in_sizes, int n_in,
                              void* d_out, int out_size)
{
    const float* x    = (const float*)d_in[0];
    const int*   ei   = (const int*)d_in[1];      // int64 in reference -> int32 in harness
    const float* W1   = (const float*)d_in[2];
    const float* b1   = (const float*)d_in[3];
    const float* W2   = (const float*)d_in[4];
    const float* b2   = (const float*)d_in[5];
    const float* W3   = (const float*)d_in[6];
    const float* b3   = (const float*)d_in[7];
    const float* Wres = (const float*)d_in[8];
    const float* bres = (const float*)d_in[9];
    const float* Wlin = (const float*)d_in[10];
    const float* blin = (const float*)d_in[11];
    float* out = (float*)d_out;

    int n = in_sizes[0] / FIN;
    int e = in_sizes[1] / 2;

    int nb256 = (n + 255) / 256;
    int eb256 = (e + 255) / 256;
    int gemmb = (n + 63) / 64;
    int gathb = (n + 7) / 8;   // 8 warps/block, one warp per node

    // graph preprocessing (deterministic each call)
    k_zero_deg<<<nb256, 256>>>(n);
    k_count<<<eb256, 256>>>(ei, e, n);
    k_norm<<<nb256, 256>>>(n);
    k_scan<<<1, 1024>>>(n);
    k_fill<<<eb256, 256>>>(ei, e, n);

    // residual path: xres = x @ Wres + bres
    k_gemm<128><<<gemmb, 256>>>(x, 0, Wres, bres, nullptr, 3, n);

    // layer 1: buf1 = x @ W1 ; buf0 = gather(buf1) + b1 + xres, relu
    k_gemm<128><<<gemmb, 256>>>(x, 0, W1, nullptr, nullptr, 2, n);
    k_gather<<<gathb, 256>>>(2, 3, b1, 1, n);

    // layer 2
    k_gemm<128><<<gemmb, 256>>>(nullptr, 1, W2, nullptr, nullptr, 2, n);
    k_gather<<<gathb, 256>>>(2, 0, b2, 1, n);

    // layer 3
    k_gemm<128><<<gemmb, 256>>>(nullptr, 1, W3, nullptr, nullptr, 2, n);
    k_gather<<<gathb, 256>>>(2, 0, b3, 1, n);

    // output projection: out = buf0 @ Wlin + blin
    k_gemm<64><<<gemmb, 256>>>(nullptr, 1, Wlin, blin, out, 0, n);
}

// round 4
// speedup vs baseline: 1.2054x; 1.2054x over previous
#include <cuda_runtime.h>
#include <cstdint>

#define NN   50000
#define EE   640000
#define FIN  128
#define HID  128
#define FOUT 64

// ---------------- device scratch (no allocations allowed) ----------------
__device__ __align__(16) float g_buf0[NN * HID];   // H (layer activations)
__device__ __align__(16) float g_buf1[NN * HID];   // P = H @ W
__device__ __align__(16) float g_xres[NN * HID];   // residual x @ Wres + bres
__device__ float g_dinv[NN];
__device__ float g_nself[NN];
__device__ int   g_deg[NN];
__device__ int   g_offs[NN];
__device__ int   g_cursor[NN];
__device__ int   g_bsum[256];
__device__ int   g_csr_src[EE];
__device__ float g_csr_ne[EE];

// buffer selectors: 0 = external pointer, 1 = g_buf0, 2 = g_buf1, 3 = g_xres
__device__ __forceinline__ const float* pick_src(int sel, const float* ext) {
    if (sel == 1) return g_buf0;
    if (sel == 2) return g_buf1;
    if (sel == 3) return g_xres;
    return ext;
}
__device__ __forceinline__ float* pick_dst(int sel, float* ext) {
    if (sel == 1) return g_buf0;
    if (sel == 2) return g_buf1;
    if (sel == 3) return g_xres;
    return ext;
}

// ---------------- graph preprocessing ----------------
__global__ void k_zero_deg(int n) {
    int i = blockIdx.x * blockDim.x + threadIdx.x;
    if (i < n) g_deg[i] = 0;
}

__global__ void k_count(const int* __restrict__ ei, int e, int n) {
    int i = blockIdx.x * blockDim.x + threadIdx.x;
    if (i < e) {
        int dst = ei[e + i];
        if (dst >= 0 && dst < n) atomicAdd(&g_deg[dst], 1);
    }
}

__global__ void k_norm(int n) {
    int i = blockIdx.x * blockDim.x + threadIdx.x;
    if (i < n) {
        float d = (float)g_deg[i] + 1.0f;   // +1 self loop
        g_dinv[i]  = rsqrtf(d);
        g_nself[i] = 1.0f / d;
    }
}

// ---- multi-block exclusive scan of g_deg -> g_offs / g_cursor ----
// pass 1: per-block (256 elems) scan, local exclusive into g_offs, block sum into g_bsum
__global__ __launch_bounds__(256) void k_scan_blk(int n) {
    int gid  = blockIdx.x * 256 + threadIdx.x;
    int lane = threadIdx.x & 31;
    int wid  = threadIdx.x >> 5;
    int v = (gid < n) ? g_deg[gid] : 0;
    int x = v;
#pragma unroll
    for (int o = 1; o < 32; o <<= 1) {
        int y = __shfl_up_sync(0xffffffffu, x, o);
        if (lane >= o) x += y;
    }
    __shared__ int wsum[8];
    if (lane == 31) wsum[wid] = x;
    __syncthreads();
    if (wid == 0) {
        int s = (lane < 8) ? wsum[lane] : 0;
#pragma unroll
        for (int o = 1; o < 8; o <<= 1) {
            int y = __shfl_up_sync(0xffffffffu, s, o);
            if (lane >= o) s += y;
        }
        if (lane < 8) wsum[lane] = s;
    }
    __syncthreads();
    int incl = x + (wid > 0 ? wsum[wid - 1] : 0);
    if (gid < n) g_offs[gid] = incl - v;   // local exclusive
    if (threadIdx.x == 255) g_bsum[blockIdx.x] = incl;
}

// pass 2: single-block exclusive scan of the (<=256) block sums
__global__ __launch_bounds__(256) void k_scan_top(int nb) {
    int tid  = threadIdx.x;
    int lane = tid & 31;
    int wid  = tid >> 5;
    int v = (tid < nb) ? g_bsum[tid] : 0;
    int x = v;
#pragma unroll
    for (int o = 1; o < 32; o <<= 1) {
        int y = __shfl_up_sync(0xffffffffu, x, o);
        if (lane >= o) x += y;
    }
    __shared__ int wsum[8];
    if (lane == 31) wsum[wid] = x;
    __syncthreads();
    if (wid == 0) {
        int s = (lane < 8) ? wsum[lane] : 0;
#pragma unroll
        for (int o = 1; o < 8; o <<= 1) {
            int y = __shfl_up_sync(0xffffffffu, s, o);
            if (lane >= o) s += y;
        }
        if (lane < 8) wsum[lane] = s;
    }
    __syncthreads();
    int incl = x + (wid > 0 ? wsum[wid - 1] : 0);
    if (tid < nb) g_bsum[tid] = incl - v;  // exclusive block offsets
}

// pass 3: add block offset, duplicate into cursor
__global__ __launch_bounds__(256) void k_scan_add(int n) {
    int gid = blockIdx.x * 256 + threadIdx.x;
    if (gid < n) {
        int o = g_offs[gid] + g_bsum[blockIdx.x];
        g_offs[gid]   = o;
        g_cursor[gid] = o;
    }
}

__global__ void k_fill(const int* __restrict__ ei, int e, int n) {
    int i = blockIdx.x * blockDim.x + threadIdx.x;
    if (i < e) {
        int src = ei[i];
        int dst = ei[e + i];
        if (src < 0 || src >= n || dst < 0 || dst >= n) return;
        int pos = atomicAdd(&g_cursor[dst], 1);
        if (pos >= 0 && pos < EE) {
            g_csr_src[pos] = src;
            g_csr_ne[pos]  = g_dinv[src] * g_dinv[dst];
        }
    }
}

// ---------------- GEMM: Y[n,FO] = X[n,128] @ W[128,FO] (+ bias) ----------------
template <int FO>
__global__ __launch_bounds__(256) void k_gemm(
    const float* Xext, int xsel, const float* __restrict__ W,
    const float* __restrict__ bias, float* Yext, int ysel, int n)
{
    const float* __restrict__ X = pick_src(xsel, Xext);
    float* __restrict__ Y       = pick_dst(ysel, Yext);

    constexpr int TJ  = FO / 4;
    constexpr int TR  = 256 / TJ;
    constexpr int RPT = 64 / TR;
    constexpr int XS_STRIDE = 33;

    __shared__ float ws[32 * FO];
    __shared__ float xs[64 * XS_STRIDE];

    int tid  = threadIdx.x;
    int row0 = blockIdx.x * 64;
    int tj   = tid % TJ;
    int tr   = tid / TJ;

    float acc[RPT][4];
#pragma unroll
    for (int r = 0; r < RPT; r++)
#pragma unroll
        for (int c = 0; c < 4; c++) acc[r][c] = 0.0f;

    for (int kc = 0; kc < 128; kc += 32) {
        constexpr int WLD = (32 * FO / 4) / 256;
        const float4* Wg = (const float4*)(W + kc * FO);
        float4* wsv = (float4*)ws;
#pragma unroll
        for (int i = 0; i < WLD; i++) wsv[tid + i * 256] = Wg[tid + i * 256];

#pragma unroll
        for (int i = 0; i < 2; i++) {
            int idx = tid + i * 256;
            int r   = idx >> 3;
            int c4  = idx & 7;
            int grow = row0 + r;
            float4 v = make_float4(0.f, 0.f, 0.f, 0.f);
            if (grow < n)
                v = ((const float4*)(X + (size_t)grow * 128 + kc))[c4];
            float* dp = &xs[r * XS_STRIDE + c4 * 4];
            dp[0] = v.x; dp[1] = v.y; dp[2] = v.z; dp[3] = v.w;
        }
        __syncthreads();

#pragma unroll
        for (int k = 0; k < 32; k++) {
            float4 w4 = ((const float4*)(ws + k * FO))[tj];
#pragma unroll
            for (int ri = 0; ri < RPT; ri++) {
                float xv = xs[(tr * RPT + ri) * XS_STRIDE + k];
                acc[ri][0] += xv * w4.x;
                acc[ri][1] += xv * w4.y;
                acc[ri][2] += xv * w4.z;
                acc[ri][3] += xv * w4.w;
            }
        }
        __syncthreads();
    }

    float4 b4 = make_float4(0.f, 0.f, 0.f, 0.f);
    if (bias) b4 = ((const float4*)bias)[tj];
#pragma unroll
    for (int ri = 0; ri < RPT; ri++) {
        int grow = row0 + tr * RPT + ri;
        if (grow < n) {
            float4 o;
            o.x = acc[ri][0] + b4.x;
            o.y = acc[ri][1] + b4.y;
            o.z = acc[ri][2] + b4.z;
            o.w = acc[ri][3] + b4.w;
            ((float4*)(Y + (size_t)grow * FO))[tj] = o;
        }
    }
}

// ---------------- fused GCN aggregation + bias + residual + ReLU ----------------
// one warp per destination node; lane owns one float4; edge loop unrolled x4 for MLP
__global__ __launch_bounds__(256) void k_gather(
    int psel, int rsel, const float* __restrict__ bias, int osel, int n)
{
    const float* __restrict__ P   = pick_src(psel, nullptr);
    const float* __restrict__ res = (rsel == 0) ? nullptr : pick_src(rsel, nullptr);
    float* __restrict__ Hout      = pick_dst(osel, nullptr);

    int warp = (blockIdx.x * blockDim.x + threadIdx.x) >> 5;
    int lane = threadIdx.x & 31;
    if (warp >= n) return;
    int node = warp;

    float ns = g_nself[node];
    float4 pv = ((const float4*)(P + (size_t)node * 128))[lane];
    float ax = pv.x * ns, ay = pv.y * ns, az = pv.z * ns, aw = pv.w * ns;
    float bx = 0.f, by = 0.f, bz = 0.f, bw = 0.f;
    float cx = 0.f, cy = 0.f, cz = 0.f, cw = 0.f;
    float dx = 0.f, dy = 0.f, dz = 0.f, dw = 0.f;

    int start = g_offs[node];
    int d     = g_deg[node];
    int i = 0;
    for (; i + 4 <= d; i += 4) {
        int e = start + i;
        int s0 = g_csr_src[e];
        int s1 = g_csr_src[e + 1];
        int s2 = g_csr_src[e + 2];
        int s3 = g_csr_src[e + 3];
        float n0 = g_csr_ne[e];
        float n1 = g_csr_ne[e + 1];
        float n2 = g_csr_ne[e + 2];
        float n3 = g_csr_ne[e + 3];
        float4 h0 = ((const float4*)(P + (size_t)s0 * 128))[lane];
        float4 h1 = ((const float4*)(P + (size_t)s1 * 128))[lane];
        float4 h2 = ((const float4*)(P + (size_t)s2 * 128))[lane];
        float4 h3 = ((const float4*)(P + (size_t)s3 * 128))[lane];
        ax += h0.x * n0; ay += h0.y * n0; az += h0.z * n0; aw += h0.w * n0;
        bx += h1.x * n1; by += h1.y * n1; bz += h1.z * n1; bw += h1.w * n1;
        cx += h2.x * n2; cy += h2.y * n2; cz += h2.z * n2; cw += h2.w * n2;
        dx += h3.x * n3; dy += h3.y * n3; dz += h3.z * n3; dw += h3.w * n3;
    }
    for (; i < d; i++) {
        int e = start + i;
        int s = g_csr_src[e];
        float ne = g_csr_ne[e];
        float4 hv = ((const float4*)(P + (size_t)s * 128))[lane];
        ax += hv.x * ne; ay += hv.y * ne; az += hv.z * ne; aw += hv.w * ne;
    }
    ax += bx + cx + dx;
    ay += by + cy + dy;
    az += bz + cz + dz;
    aw += bw + cw + dw;

    float4 b4 = ((const float4*)bias)[lane];
    ax += b4.x; ay += b4.y; az += b4.z; aw += b4.w;
    if (res) {
        float4 r4 = ((const float4*)(res + (size_t)node * 128))[lane];
        ax += r4.x; ay += r4.y; az += r4.z; aw += r4.w;
    }
    float4 o;
    o.x = fmaxf(ax, 0.f);
    o.y = fmaxf(ay, 0.f);
    o.z = fmaxf(az, 0.f);
    o.w = fmaxf(aw, 0.f);
    ((float4*)(Hout + (size_t)node * 128))[lane] = o;
}

// ---------------- launch ----------------
extern "C" void kernel_launch(void* const* d_in, const int* in_sizes, int n_in,
                              void* d_out, int out_size)
{
    const float* x    = (const float*)d_in[0];
    const int*   ei   = (const int*)d_in[1];
    const float* W1   = (const float*)d_in[2];
    const float* b1   = (const float*)d_in[3];
    const float* W2   = (const float*)d_in[4];
    const float* b2   = (const float*)d_in[5];
    const float* W3   = (const float*)d_in[6];
    const float* b3   = (const float*)d_in[7];
    const float* Wres = (const float*)d_in[8];
    const float* bres = (const float*)d_in[9];
    const float* Wlin = (const float*)d_in[10];
    const float* blin = (const float*)d_in[11];
    float* out = (float*)d_out;

    int n = in_sizes[0] / FIN;
    int e = in_sizes[1] / 2;

    int nb256 = (n + 255) / 256;
    int eb256 = (e + 255) / 256;
    int gemmb = (n + 63) / 64;
    int gathb = (n + 7) / 8;

    // graph preprocessing
    k_zero_deg<<<nb256, 256>>>(n);
    k_count<<<eb256, 256>>>(ei, e, n);
    k_norm<<<nb256, 256>>>(n);
    k_scan_blk<<<nb256, 256>>>(n);
    k_scan_top<<<1, 256>>>(nb256);
    k_scan_add<<<nb256, 256>>>(n);
    k_fill<<<eb256, 256>>>(ei, e, n);

    // residual path: xres = x @ Wres + bres
    k_gemm<128><<<gemmb, 256>>>(x, 0, Wres, bres, nullptr, 3, n);

    // layer 1
    k_gemm<128><<<gemmb, 256>>>(x, 0, W1, nullptr, nullptr, 2, n);
    k_gather<<<gathb, 256>>>(2, 3, b1, 1, n);

    // layer 2
    k_gemm<128><<<gemmb, 256>>>(nullptr, 1, W2, nullptr, nullptr, 2, n);
    k_gather<<<gathb, 256>>>(2, 0, b2, 1, n);

    // layer 3
    k_gemm<128><<<gemmb, 256>>>(nullptr, 1, W3, nullptr, nullptr, 2, n);
    k_gather<<<gathb, 256>>>(2, 0, b3, 1, n);

    // output projection
    k_gemm<64><<<gemmb, 256>>>(nullptr, 1, Wlin, blin, out, 0, n);
}